// round 10
// baseline (speedup 1.0000x reference)
#include <cuda_runtime.h>
#include <cuda_bf16.h>

#define NTOT 524288
#define DIM  128
#define S    128
#define G    (NTOT / S)
#define MARGIN   2.0f
#define K_MARGIN 0.02f
#define EPS      1e-6f

// Per-group scratch + sync (static device allocation — allowed).
__device__ float g_loss[G];
__device__ float g_sumb[G];
__device__ float g_sump[G];
__device__ int   g_cntb[G];
__device__ int   g_prod[G];    // producer-CTA completion count; self-resetting
__device__ int   g_flag[G];    // d-ready flag; consumer resets -> replay-safe
__device__ int   g_done = 0;   // reset by last consumer each launch

// ---------------------------------------------------------------------------
// Batched block-wide sum over 256 threads (8 warps). All threads get results.
// ---------------------------------------------------------------------------
template<int K>
__device__ __forceinline__ void blockSumK(float* v, float (*red)[8])
{
    #pragma unroll
    for (int k = 0; k < K; k++)
        #pragma unroll
        for (int o = 16; o; o >>= 1)
            v[k] += __shfl_xor_sync(0xffffffffu, v[k], o);
    int w = threadIdx.x >> 5;
    if ((threadIdx.x & 31) == 0)
        #pragma unroll
        for (int k = 0; k < K; k++) red[k][w] = v[k];
    __syncthreads();
    #pragma unroll
    for (int k = 0; k < K; k++)
        v[k] = (red[k][0] + red[k][1]) + (red[k][2] + red[k][3])
             + (red[k][4] + red[k][5]) + (red[k][6] + red[k][7]);
    __syncthreads();
}

// ---------------------------------------------------------------------------
// Unified kernel, grid = 17*G. Per group q (super-block of 17 CTAs):
//   bids 17q .. 17q+15 : producers — 8 rows each (one row per warp; the exact
//                        shape that measured 85.3% DRAM). 16th completion
//                        sets g_flag[q].
//   bid  17q+16        : consumer — full group phase for group q (spin on flag).
// Consumers are dispatched right after their own producers -> full overlap.
// ---------------------------------------------------------------------------
__global__ void __launch_bounds__(256) metrics_kernel(
    const float4* __restrict__ zr, const float4* __restrict__ zv,
    const int* __restrict__ var_lens, const int* __restrict__ labels,
    float* __restrict__ out)
{
    const int bid  = blockIdx.x;
    const int q    = bid / 17;          // group id
    const int role = bid - q * 17;      // 0..15 producer chunk, 16 consumer
    const int tid  = threadIdx.x;
    const int w    = tid >> 5;
    const int lane = tid & 31;
    float* dout = out + 2;

    // ======================= Producer =======================
    if (role < 16) {
        int row = q * S + role * 8 + w;               // one row per warp
        size_t off = (size_t)row * 32 + lane;         // 32 float4 per row
        float4 a = zr[off];
        float4 b = zv[off];
        float s = a.x*b.x + a.y*b.y + a.z*b.z + a.w*b.w;
        #pragma unroll
        for (int o = 16; o; o >>= 1) s += __shfl_xor_sync(0xffffffffu, s, o);
        if (lane == 0) dout[row] = 1.0f - s;
        __syncthreads();
        if (tid == 0) {
            __threadfence();                          // release d stores
            if (atomicAdd(&g_prod[q], 1) == 15) {
                g_prod[q] = 0;                        // reset for next replay
                *((volatile int*)&g_flag[q]) = 1;     // publish group q
            }
        }
        return;
    }

    // ======================= Consumer =======================
    __shared__ int   sv[S];      // v (original order)
    __shared__ float sds[S];     // d sorted by v (stable)
    __shared__ int   se[S];      // tie-run end (exclusive) at sorted position
    __shared__ int   cnt[101];   // counting-sort bins
    __shared__ int   P[101];     // exclusive bin prefix; P[100] = S
    __shared__ float red[5][8];
    __shared__ int   isLast;

    const int g = q;

    if (tid < 101) cnt[tid] = 0;
    if (tid == 0) {
        while (*((volatile int*)&g_flag[g]) == 0) __nanosleep(100);
        __threadfence();                // acquire
    }
    __syncthreads();

    const bool act = tid < S;
    int   v  = 0, lb = -1;
    float di = 0.0f;
    if (act) {
        int idx = g * S + tid;
        di = dout[idx];                 // L2-hot
        v  = min(max(var_lens[idx], 0), 99);
        lb = labels[idx];
        sv[tid] = v;
        atomicAdd(&cnt[v], 1);
    }
    __syncthreads();
    if (tid == 0) *((volatile int*)&g_flag[g]) = 0;   // reset for next replay

    // ---- pass 1: label sums + means (5 sums, one barrier pair) ----
    float vf = act ? (float)v : 0.0f;
    float p1[5] = { lb == 0 ? di : 0.0f, lb == 1 ? di : 0.0f,
                    lb == 0 ? 1.0f : 0.0f, vf, act ? di : 0.0f };
    blockSumK<5>(p1, red);
    float sb = p1[0], sp = p1[1], cb = p1[2];
    float meanv = p1[3] * (1.0f / S);
    float meand = p1[4] * (1.0f / S);

    // ---- pass 2: variances (ddof=1) ----
    float dv0 = act ? vf - meanv : 0.0f;
    float dd0 = act ? di - meand : 0.0f;
    float p2[2] = { dv0 * dv0, dd0 * dd0 };
    blockSumK<2>(p2, red);
    float vs = sqrtf(p2[0] * (1.0f / (S - 1)));
    float ds = sqrtf(p2[1] * (1.0f / (S - 1)));
    float vz = dv0 / (vs + EPS);
    float dz = dd0 / (ds + EPS);

    // ---- pass 3: corr ----
    float p3[1] = { act ? (vz - dz) * (vz - dz) : 0.0f };
    blockSumK<1>(p3, red);
    float corr = p3[0] * (1.0f / S);
    if (!(vs > 0.0f && ds > 0.0f)) corr = 0.0f;

    // ---- bin prefix sums (serial over 100 bins) ----
    if (tid == 0) {
        int run = 0;
        #pragma unroll 4
        for (int b = 0; b < 100; b++) { P[b] = run; run += cnt[b]; }
        P[100] = run;   // == S
    }
    __syncthreads();

    // ---- stable scatter: rank among earlier equal keys ----
    if (act) {
        int rank = 0;
        #pragma unroll 8
        for (int j = 0; j < S; j++) rank += (j < tid) & (sv[j] == v);
        int pos = P[v] + rank;
        sds[pos] = di;
        se[pos]  = P[v + 1];   // end (exclusive) of this tie run
    }
    __syncthreads();

    // ---- pass 4: neigh_viol + rank_loss (3 sums, one barrier pair) ----
    float nv = (tid < S - 1) ? fmaxf(sds[tid] - sds[tid + 1] + K_MARGIN, 0.0f) : 0.0f;
    const int   i   = tid & (S - 1);
    const int   h   = tid >> 7;
    const int   e   = se[i];
    const float ddi = sds[i] + K_MARGIN;
    float viol = 0.0f;
    for (int j = e + h; j < S; j += 2)
        viol += fmaxf(ddi - sds[j], 0.0f);
    float p4[3] = { nv, h == 0 ? (float)(S - e) : 0.0f, viol };
    blockSumK<3>(p4, red);
    float neigh = p4[0] * (1.0f / (S - 1));
    float rankl = (p4[1] > 0.0f) ? p4[2] / p4[1] : 0.0f;

    if (tid == 0) {
        g_loss[g] = corr + neigh + rankl;
        g_sumb[g] = sb;
        g_sump[g] = sp;
        g_cntb[g] = (int)cb;
        __threadfence();
        int old = atomicAdd(&g_done, 1);
        isLast = (old == G - 1);
    }
    __syncthreads();

    // ---------------- last consumer finalizes ----------------
    if (isLast) {
        __shared__ double shL[256], shB[256], shP[256];
        __shared__ long long shC[256];

        double aL = 0.0, aB = 0.0, aP = 0.0;
        long long cB = 0;
        #pragma unroll 4
        for (int u = tid; u < G; u += 256) {
            aL += (double)g_loss[u];
            aB += (double)g_sumb[u];
            aP += (double)g_sump[u];
            cB += (long long)g_cntb[u];
        }
        shL[tid] = aL; shB[tid] = aB; shP[tid] = aP; shC[tid] = cB;
        __syncthreads();
        #pragma unroll
        for (int s = 128; s > 0; s >>= 1) {
            if (tid < s) {
                shL[tid] += shL[tid + s];
                shB[tid] += shB[tid + s];
                shP[tid] += shP[tid + s];
                shC[tid] += shC[tid + s];
            }
            __syncthreads();
        }
        if (tid == 0) {
            long long nb = shC[0];
            long long np = (long long)NTOT - nb;
            double mb = shB[0] / (double)(nb > 1 ? nb : 1);
            double mp = shP[0] / (double)(np > 1 ? np : 1);
            double lcdd = (nb > 0 && np > 0) ? (MARGIN + mb - mp) : 0.0;
            if (lcdd < 0.0) lcdd = 0.0;
            out[0] = (float)lcdd;
            out[1] = (float)(shL[0] / (double)G);
            g_done = 0;            // reset for next graph replay
        }
    }
}

// ---------------------------------------------------------------------------
extern "C" void kernel_launch(void* const* d_in, const int* in_sizes, int n_in,
                              void* d_out, int out_size)
{
    const float* zr       = (const float*)d_in[0];
    const float* zv       = (const float*)d_in[1];
    const int*   labels   = (const int*)d_in[2];
    // d_in[3] = groups (== i / S by construction, unused)
    const int*   var_lens = (const int*)d_in[4];
    float* out = (float*)d_out;

    metrics_kernel<<<17 * G, 256>>>((const float4*)zr, (const float4*)zv,
                                    var_lens, labels, out);
}

// round 11
// speedup vs baseline: 1.2021x; 1.2021x over previous
#include <cuda_runtime.h>
#include <cuda_bf16.h>

#define NTOT 524288
#define DIM  128
#define S    128
#define G    (NTOT / S)
#define NCHUNK 8
#define GCH    (G / NCHUNK)          // 512 groups per chunk
#define RCH    (NTOT / NCHUNK)       // 65536 rows per chunk
#define MARGIN   2.0f
#define K_MARGIN 0.02f
#define EPS      1e-6f

// Per-group scratch + completion counter (static device allocation — allowed).
__device__ float g_loss[G];
__device__ float g_sumb[G];
__device__ float g_sump[G];
__device__ int   g_cntb[G];
__device__ int   g_done = 0;   // reset by last CTA each launch -> replay-safe

// ---------------------------------------------------------------------------
// Streams + events, created once at static-init time (before harness baseline).
// No device-memory allocation happens here.
// ---------------------------------------------------------------------------
struct PipeRes {
    cudaStream_t s1, s2;
    cudaEvent_t  evFork, evJoin, evDot[NCHUNK];
    PipeRes() {
        cudaStreamCreateWithFlags(&s1, cudaStreamNonBlocking);
        cudaStreamCreateWithFlags(&s2, cudaStreamNonBlocking);
        cudaEventCreateWithFlags(&evFork, cudaEventDisableTiming);
        cudaEventCreateWithFlags(&evJoin, cudaEventDisableTiming);
        for (int i = 0; i < NCHUNK; i++)
            cudaEventCreateWithFlags(&evDot[i], cudaEventDisableTiming);
    }
};
static PipeRes g_res;

// ---------------------------------------------------------------------------
// Kernel 1: d[i] = 1 - dot(z_r[i], z_v[i]).  One warp per row, float4 loads.
// EXACT shape that measured 85.3% DRAM / 6.76 TB/s (16 regs). Chunked.
// ---------------------------------------------------------------------------
__global__ void __launch_bounds__(256) dot_kernel(
    const float4* __restrict__ zr, const float4* __restrict__ zv,
    float* __restrict__ dout)
{
    int gw   = (blockIdx.x * blockDim.x + threadIdx.x) >> 5;   // row id in chunk
    int lane = threadIdx.x & 31;
    size_t off = (size_t)gw * 32 + lane;                       // 32 float4 per row
    float4 a = zr[off];
    float4 b = zv[off];
    float s = a.x * b.x + a.y * b.y + a.z * b.z + a.w * b.w;
    #pragma unroll
    for (int o = 16; o; o >>= 1) s += __shfl_xor_sync(0xffffffffu, s, o);
    if (lane == 0) dout[gw] = 1.0f - s;
}

// ---------------------------------------------------------------------------
// Batched block-wide sum over 256 threads (8 warps). All threads get results.
// ---------------------------------------------------------------------------
template<int K>
__device__ __forceinline__ void blockSumK(float* v, float (*red)[8])
{
    #pragma unroll
    for (int k = 0; k < K; k++)
        #pragma unroll
        for (int o = 16; o; o >>= 1)
            v[k] += __shfl_xor_sync(0xffffffffu, v[k], o);
    int w = threadIdx.x >> 5;
    if ((threadIdx.x & 31) == 0)
        #pragma unroll
        for (int k = 0; k < K; k++) red[k][w] = v[k];
    __syncthreads();
    #pragma unroll
    for (int k = 0; k < K; k++)
        v[k] = (red[k][0] + red[k][1]) + (red[k][2] + red[k][3])
             + (red[k][4] + red[k][5]) + (red[k][6] + red[k][7]);
    __syncthreads();
}

// ---------------------------------------------------------------------------
// Kernel 2: one CTA (256 threads) per group (chunked by gbase); d from hot L2.
// EXACT R7 body (proven). Last CTA overall finalizes out[0], out[1].
// ---------------------------------------------------------------------------
__global__ void __launch_bounds__(256) group_kernel(
    const int* __restrict__ var_lens, const int* __restrict__ labels,
    float* __restrict__ out, int gbase)
{
    __shared__ int   sv[S];      // v (original order)
    __shared__ float sds[S];     // d sorted by v (stable)
    __shared__ int   se[S];      // tie-run end (exclusive) at sorted position
    __shared__ int   cnt[101];   // counting-sort bins
    __shared__ int   P[101];     // exclusive bin prefix; P[100] = S
    __shared__ float red[5][8];
    __shared__ int   isLast;

    const int g   = gbase + blockIdx.x;
    const int tid = threadIdx.x;
    const float* dvec = out + 2;

    if (tid < 101) cnt[tid] = 0;
    __syncthreads();

    const bool act = tid < S;
    int   v  = 0, lb = -1;
    float di = 0.0f;
    if (act) {
        int idx = g * S + tid;
        di = dvec[idx];            // L2-hot (written by dot chunk just finished)
        v  = min(max(var_lens[idx], 0), 99);
        lb = labels[idx];
        sv[tid] = v;
        atomicAdd(&cnt[v], 1);
    }

    // ---- pass 1: label sums + means (5 sums, one barrier pair) ----
    float vf = act ? (float)v : 0.0f;
    float p1[5] = { lb == 0 ? di : 0.0f, lb == 1 ? di : 0.0f,
                    lb == 0 ? 1.0f : 0.0f, vf, act ? di : 0.0f };
    blockSumK<5>(p1, red);
    float sb = p1[0], sp = p1[1], cb = p1[2];
    float meanv = p1[3] * (1.0f / S);
    float meand = p1[4] * (1.0f / S);

    // ---- pass 2: variances (ddof=1) ----
    float dv0 = act ? vf - meanv : 0.0f;
    float dd0 = act ? di - meand : 0.0f;
    float p2[2] = { dv0 * dv0, dd0 * dd0 };
    blockSumK<2>(p2, red);
    float vs = sqrtf(p2[0] * (1.0f / (S - 1)));
    float ds = sqrtf(p2[1] * (1.0f / (S - 1)));
    float vz = dv0 / (vs + EPS);
    float dz = dd0 / (ds + EPS);

    // ---- pass 3: corr ----
    float p3[1] = { act ? (vz - dz) * (vz - dz) : 0.0f };
    blockSumK<1>(p3, red);
    float corr = p3[0] * (1.0f / S);
    if (!(vs > 0.0f && ds > 0.0f)) corr = 0.0f;

    // ---- bin prefix sums (serial over 100 bins) ----
    if (tid == 0) {
        int run = 0;
        #pragma unroll 4
        for (int q = 0; q < 100; q++) { P[q] = run; run += cnt[q]; }
        P[100] = run;   // == S
    }
    __syncthreads();

    // ---- stable scatter: rank among earlier equal keys ----
    if (act) {
        int rank = 0;
        #pragma unroll 8
        for (int j = 0; j < S; j++) rank += (j < tid) & (sv[j] == v);
        int pos = P[v] + rank;
        sds[pos] = di;
        se[pos]  = P[v + 1];   // end (exclusive) of this tie run
    }
    __syncthreads();

    // ---- pass 4: neigh_viol + rank_loss (3 sums, one barrier pair) ----
    float nv = (tid < S - 1) ? fmaxf(sds[tid] - sds[tid + 1] + K_MARGIN, 0.0f) : 0.0f;
    const int   i   = tid & (S - 1);
    const int   h   = tid >> 7;
    const int   e   = se[i];
    const float ddi = sds[i] + K_MARGIN;
    float viol = 0.0f;
    for (int j = e + h; j < S; j += 2)
        viol += fmaxf(ddi - sds[j], 0.0f);
    float p4[3] = { nv, h == 0 ? (float)(S - e) : 0.0f, viol };
    blockSumK<3>(p4, red);
    float neigh = p4[0] * (1.0f / (S - 1));
    float rankl = (p4[1] > 0.0f) ? p4[2] / p4[1] : 0.0f;

    if (tid == 0) {
        g_loss[g] = corr + neigh + rankl;
        g_sumb[g] = sb;
        g_sump[g] = sp;
        g_cntb[g] = (int)cb;
        __threadfence();
        int old = atomicAdd(&g_done, 1);
        isLast = (old == G - 1);
    }
    __syncthreads();

    // ---------------- overall-last CTA finalizes ----------------
    if (isLast) {
        __shared__ double shL[256], shB[256], shP[256];
        __shared__ long long shC[256];

        double aL = 0.0, aB = 0.0, aP = 0.0;
        long long cB = 0;
        #pragma unroll 4
        for (int q = tid; q < G; q += 256) {
            aL += (double)g_loss[q];
            aB += (double)g_sumb[q];
            aP += (double)g_sump[q];
            cB += (long long)g_cntb[q];
        }
        shL[tid] = aL; shB[tid] = aB; shP[tid] = aP; shC[tid] = cB;
        __syncthreads();
        #pragma unroll
        for (int s = 128; s > 0; s >>= 1) {
            if (tid < s) {
                shL[tid] += shL[tid + s];
                shB[tid] += shB[tid + s];
                shP[tid] += shP[tid + s];
                shC[tid] += shC[tid + s];
            }
            __syncthreads();
        }
        if (tid == 0) {
            long long nb = shC[0];
            long long np = (long long)NTOT - nb;
            double mb = shB[0] / (double)(nb > 1 ? nb : 1);
            double mp = shP[0] / (double)(np > 1 ? np : 1);
            double lcdd = (nb > 0 && np > 0) ? (MARGIN + mb - mp) : 0.0;
            if (lcdd < 0.0) lcdd = 0.0;
            out[0] = (float)lcdd;
            out[1] = (float)(shL[0] / (double)G);
            g_done = 0;            // reset for next graph replay
        }
    }
}

// ---------------------------------------------------------------------------
// Chunked two-stream pipeline: dot_c on s1, group_c on s2 gated by evDot[c].
// Standard capture-legal fork/join off the (captured) default stream.
// ---------------------------------------------------------------------------
extern "C" void kernel_launch(void* const* d_in, const int* in_sizes, int n_in,
                              void* d_out, int out_size)
{
    const float* zr       = (const float*)d_in[0];
    const float* zv       = (const float*)d_in[1];
    const int*   labels   = (const int*)d_in[2];
    // d_in[3] = groups (== i / S by construction, unused)
    const int*   var_lens = (const int*)d_in[4];
    float* out  = (float*)d_out;
    float* dvec = out + 2;

    // Fork both worker streams off the captured origin stream.
    cudaEventRecord(g_res.evFork, 0);
    cudaStreamWaitEvent(g_res.s1, g_res.evFork, 0);
    cudaStreamWaitEvent(g_res.s2, g_res.evFork, 0);

    for (int c = 0; c < NCHUNK; c++) {
        const float4* zrc = (const float4*)zr + (size_t)c * RCH * 32;
        const float4* zvc = (const float4*)zv + (size_t)c * RCH * 32;
        dot_kernel<<<RCH / 8, 256, 0, g_res.s1>>>(zrc, zvc, dvec + (size_t)c * RCH);
        cudaEventRecord(g_res.evDot[c], g_res.s1);

        cudaStreamWaitEvent(g_res.s2, g_res.evDot[c], 0);
        group_kernel<<<GCH, 256, 0, g_res.s2>>>(var_lens, labels, out, c * GCH);
    }

    // Join back into the origin stream (s1's tail is ordered before s2's tail).
    cudaEventRecord(g_res.evJoin, g_res.s2);
    cudaStreamWaitEvent(0, g_res.evJoin, 0);
}

// round 15
// speedup vs baseline: 1.3184x; 1.0967x over previous
#include <cuda_runtime.h>
#include <cuda_bf16.h>

#define NTOT 524288
#define DIM  128
#define S    128
#define G    (NTOT / S)
#define NCHUNK 4
#define GCH    (G / NCHUNK)          // 1024 groups per chunk
#define RCH    (NTOT / NCHUNK)       // 131072 rows per chunk
#define MARGIN   2.0f
#define K_MARGIN 0.02f
#define EPS      1e-6f

// Per-group scratch + completion counter (static device allocation — allowed).
__device__ float g_loss[G];
__device__ float g_sumb[G];
__device__ float g_sump[G];
__device__ int   g_cntb[G];
__device__ int   g_done = 0;   // reset by last CTA each launch -> replay-safe

// ---------------------------------------------------------------------------
// Streams + events, created once at static-init time. No device memory.
// ---------------------------------------------------------------------------
struct PipeRes {
    cudaStream_t s1, s2;
    cudaEvent_t  evFork, evJoin, evDot[NCHUNK];
    PipeRes() {
        cudaStreamCreateWithFlags(&s1, cudaStreamNonBlocking);
        cudaStreamCreateWithFlags(&s2, cudaStreamNonBlocking);
        cudaEventCreateWithFlags(&evFork, cudaEventDisableTiming);
        cudaEventCreateWithFlags(&evJoin, cudaEventDisableTiming);
        for (int i = 0; i < NCHUNK; i++)
            cudaEventCreateWithFlags(&evDot[i], cudaEventDisableTiming);
    }
};
static PipeRes g_res;

// ---------------------------------------------------------------------------
// Kernel 1: d[i] = 1 - dot(z_r[i], z_v[i]).  One warp per row, float4 loads.
// EXACT shape that measured 85.3% DRAM / 6.76 TB/s (16 regs). Chunked.
// ---------------------------------------------------------------------------
__global__ void __launch_bounds__(256) dot_kernel(
    const float4* __restrict__ zr, const float4* __restrict__ zv,
    float* __restrict__ dout)
{
    int gw   = (blockIdx.x * blockDim.x + threadIdx.x) >> 5;   // row id in chunk
    int lane = threadIdx.x & 31;
    size_t off = (size_t)gw * 32 + lane;                       // 32 float4 per row
    float4 a = zr[off];
    float4 b = zv[off];
    float s = a.x * b.x + a.y * b.y + a.z * b.z + a.w * b.w;
    #pragma unroll
    for (int o = 16; o; o >>= 1) s += __shfl_xor_sync(0xffffffffu, s, o);
    if (lane == 0) dout[gw] = 1.0f - s;
}

// ---------------------------------------------------------------------------
// Batched block-wide sum over 128 threads (4 warps). All threads get results.
// ---------------------------------------------------------------------------
template<int K>
__device__ __forceinline__ void blockSumK(float* v, float (*red)[4])
{
    #pragma unroll
    for (int k = 0; k < K; k++)
        #pragma unroll
        for (int o = 16; o; o >>= 1)
            v[k] += __shfl_xor_sync(0xffffffffu, v[k], o);
    int w = threadIdx.x >> 5;
    if ((threadIdx.x & 31) == 0)
        #pragma unroll
        for (int k = 0; k < K; k++) red[k][w] = v[k];
    __syncthreads();
    #pragma unroll
    for (int k = 0; k < K; k++)
        v[k] = (red[k][0] + red[k][1]) + (red[k][2] + red[k][3]);
    __syncthreads();
}

// ---------------------------------------------------------------------------
// Kernel 2: one CTA (128 threads = S) per group; d from hot L2.
//  - stable rank: __match_any intra-warp + int4 scan of earlier warps only
//  - violation loop float4-vectorized from aligned start
//  - overall-last CTA finalizes out[0], out[1] (double precision).
// ---------------------------------------------------------------------------
__global__ void __launch_bounds__(128) group_kernel(
    const int* __restrict__ var_lens, const int* __restrict__ labels,
    float* __restrict__ out, int gbase)
{
    __shared__ int   sv[S];      // v (original order)
    __shared__ float sds[S];     // d sorted by v (stable)
    __shared__ int   se[S];      // tie-run end (exclusive) at sorted position
    __shared__ int   cnt[101];   // counting-sort bins
    __shared__ int   P[101];     // exclusive bin prefix; P[100] = S
    __shared__ float red[5][4];
    __shared__ int   isLast;

    const int g    = gbase + blockIdx.x;
    const int tid  = threadIdx.x;     // == row index, all threads active
    const int w    = tid >> 5;
    const int lane = tid & 31;
    const float* dvec = out + 2;

    if (tid < 101) cnt[tid] = 0;
    __syncthreads();

    const int idx = g * S + tid;
    const float di = dvec[idx];              // L2-hot
    const int   v  = min(max(var_lens[idx], 0), 99);
    const int   lb = labels[idx];
    sv[tid] = v;
    atomicAdd(&cnt[v], 1);

    // ---- stable rank, intra-warp part (no barrier needed yet) ----
    unsigned m = __match_any_sync(0xffffffffu, v);
    int rank = __popc(m & ((1u << lane) - 1u));

    // ---- pass 1: label sums + means (5 sums; its barrier publishes sv/cnt) --
    float vf = (float)v;
    float p1[5] = { lb == 0 ? di : 0.0f, lb == 1 ? di : 0.0f,
                    lb == 0 ? 1.0f : 0.0f, vf, di };
    blockSumK<5>(p1, red);
    float sb = p1[0], sp = p1[1], cb = p1[2];
    float meanv = p1[3] * (1.0f / S);
    float meand = p1[4] * (1.0f / S);

    // ---- rank, earlier-warp part: int4 scan of sv[0 .. 32w) ----
    {
        const int4* sv4 = (const int4*)sv;
        const int nch = w << 3;              // w * 8 chunks of 4
        for (int j4 = 0; j4 < nch; j4++) {
            int4 q = sv4[j4];
            rank += (q.x == v) + (q.y == v) + (q.z == v) + (q.w == v);
        }
    }

    // ---- pass 2: variances (ddof=1) ----
    float dv0 = vf - meanv;
    float dd0 = di - meand;
    float p2[2] = { dv0 * dv0, dd0 * dd0 };
    blockSumK<2>(p2, red);
    float vs = sqrtf(p2[0] * (1.0f / (S - 1)));
    float ds = sqrtf(p2[1] * (1.0f / (S - 1)));
    float vz = dv0 / (vs + EPS);
    float dz = dd0 / (ds + EPS);

    // ---- pass 3: corr ----
    float p3[1] = { (vz - dz) * (vz - dz) };
    blockSumK<1>(p3, red);
    float corr = p3[0] * (1.0f / S);
    if (!(vs > 0.0f && ds > 0.0f)) corr = 0.0f;

    // ---- bin prefix sums (serial over 100 bins by tid0) ----
    if (tid == 0) {
        int run = 0;
        #pragma unroll 4
        for (int q = 0; q < 100; q++) { P[q] = run; run += cnt[q]; }
        P[100] = run;   // == S
    }
    __syncthreads();

    // ---- stable scatter ----
    {
        int pos = P[v] + rank;
        sds[pos] = di;
        se[pos]  = P[v + 1];   // end (exclusive) of this tie run
    }
    __syncthreads();

    // ---- neigh_viol + rank_loss ----
    float nv = (tid < S - 1) ? fmaxf(sds[tid] - sds[tid + 1] + K_MARGIN, 0.0f) : 0.0f;
    const int   e   = se[tid];
    const float ddi = sds[tid] + K_MARGIN;
    float viol = 0.0f;
    {
        int j = e;
        for (; (j & 3) && j < S; j++)            // head to 16B alignment
            viol += fmaxf(ddi - sds[j], 0.0f);
        const float4* s4 = (const float4*)sds;
        for (; j < S; j += 4) {
            float4 q = s4[j >> 2];
            viol += fmaxf(ddi - q.x, 0.0f) + fmaxf(ddi - q.y, 0.0f)
                  + fmaxf(ddi - q.z, 0.0f) + fmaxf(ddi - q.w, 0.0f);
        }
    }
    float p4[3] = { nv, (float)(S - e), viol };
    blockSumK<3>(p4, red);
    float neigh = p4[0] * (1.0f / (S - 1));
    float rankl = (p4[1] > 0.0f) ? p4[2] / p4[1] : 0.0f;

    if (tid == 0) {
        g_loss[g] = corr + neigh + rankl;
        g_sumb[g] = sb;
        g_sump[g] = sp;
        g_cntb[g] = (int)cb;
        __threadfence();
        int old = atomicAdd(&g_done, 1);
        isLast = (old == G - 1);
    }
    __syncthreads();

    // ---------------- overall-last CTA finalizes ----------------
    if (isLast) {
        __shared__ double shL[128], shB[128], shP[128];
        __shared__ long long shC[128];

        double aL = 0.0, aB = 0.0, aP = 0.0;
        long long cB = 0;
        #pragma unroll 4
        for (int q = tid; q < G; q += 128) {
            aL += (double)g_loss[q];
            aB += (double)g_sumb[q];
            aP += (double)g_sump[q];
            cB += (long long)g_cntb[q];
        }
        shL[tid] = aL; shB[tid] = aB; shP[tid] = aP; shC[tid] = cB;
        __syncthreads();
        #pragma unroll
        for (int s = 64; s > 0; s >>= 1) {
            if (tid < s) {
                shL[tid] += shL[tid + s];
                shB[tid] += shB[tid + s];
                shP[tid] += shP[tid + s];
                shC[tid] += shC[tid + s];
            }
            __syncthreads();
        }
        if (tid == 0) {
            long long nb = shC[0];
            long long np = (long long)NTOT - nb;
            double mb = shB[0] / (double)(nb > 1 ? nb : 1);
            double mp = shP[0] / (double)(np > 1 ? np : 1);
            double lcdd = (nb > 0 && np > 0) ? (MARGIN + mb - mp) : 0.0;
            if (lcdd < 0.0) lcdd = 0.0;
            out[0] = (float)lcdd;
            out[1] = (float)(shL[0] / (double)G);
            g_done = 0;            // reset for next graph replay
        }
    }
}

// ---------------------------------------------------------------------------
// Chunked two-stream pipeline: dot_c on s1, group_c on s2 gated by evDot[c].
// ---------------------------------------------------------------------------
extern "C" void kernel_launch(void* const* d_in, const int* in_sizes, int n_in,
                              void* d_out, int out_size)
{
    const float* zr       = (const float*)d_in[0];
    const float* zv       = (const float*)d_in[1];
    const int*   labels   = (const int*)d_in[2];
    // d_in[3] = groups (== i / S by construction, unused)
    const int*   var_lens = (const int*)d_in[4];
    float* out  = (float*)d_out;
    float* dvec = out + 2;

    cudaEventRecord(g_res.evFork, 0);
    cudaStreamWaitEvent(g_res.s1, g_res.evFork, 0);
    cudaStreamWaitEvent(g_res.s2, g_res.evFork, 0);

    for (int c = 0; c < NCHUNK; c++) {
        const float4* zrc = (const float4*)zr + (size_t)c * RCH * 32;
        const float4* zvc = (const float4*)zv + (size_t)c * RCH * 32;
        dot_kernel<<<RCH / 8, 256, 0, g_res.s1>>>(zrc, zvc, dvec + (size_t)c * RCH);
        cudaEventRecord(g_res.evDot[c], g_res.s1);

        cudaStreamWaitEvent(g_res.s2, g_res.evDot[c], 0);
        group_kernel<<<GCH, 128, 0, g_res.s2>>>(var_lens, labels, out, c * GCH);
    }

    cudaEventRecord(g_res.evJoin, g_res.s2);
    cudaStreamWaitEvent(0, g_res.evJoin, 0);
}

// round 17
// speedup vs baseline: 1.3830x; 1.0491x over previous
#include <cuda_runtime.h>
#include <cuda_bf16.h>

#define NTOT 524288
#define DIM  128
#define S    128
#define G    (NTOT / S)
#define NCHUNK 4
#define GCH    (G / NCHUNK)          // 1024 groups per chunk
#define RCH    (NTOT / NCHUNK)       // 131072 rows per chunk
#define MARGIN   2.0f
#define K_MARGIN 0.02f
#define EPS      1e-6f

// Per-group scratch + completion counter (static device allocation — allowed).
__device__ float g_loss[G];
__device__ float g_sumb[G];
__device__ float g_sump[G];
__device__ int   g_cntb[G];
__device__ int   g_done = 0;   // reset by last CTA each launch -> replay-safe

// ---------------------------------------------------------------------------
// Streams + events, created once at static-init time. No device memory.
// s1 (dot stream) gets the highest priority so streaming CTAs win slots.
// ---------------------------------------------------------------------------
struct PipeRes {
    cudaStream_t s1, s2;
    cudaEvent_t  evFork, evJoin, evDot[NCHUNK];
    PipeRes() {
        int lo = 0, hi = 0;
        cudaDeviceGetStreamPriorityRange(&lo, &hi);
        cudaStreamCreateWithPriority(&s1, cudaStreamNonBlocking, hi);
        cudaStreamCreateWithPriority(&s2, cudaStreamNonBlocking, lo);
        cudaEventCreateWithFlags(&evFork, cudaEventDisableTiming);
        cudaEventCreateWithFlags(&evJoin, cudaEventDisableTiming);
        for (int i = 0; i < NCHUNK; i++)
            cudaEventCreateWithFlags(&evDot[i], cudaEventDisableTiming);
    }
};
static PipeRes g_res;

// ---------------------------------------------------------------------------
// Kernel 1: d[i] = 1 - dot(z_r[i], z_v[i]).  One warp per row, float4 loads.
// EXACT shape that measured 85.3% DRAM / 6.76 TB/s (16 regs). Chunked.
// ---------------------------------------------------------------------------
__global__ void __launch_bounds__(256) dot_kernel(
    const float4* __restrict__ zr, const float4* __restrict__ zv,
    float* __restrict__ dout)
{
    int gw   = (blockIdx.x * blockDim.x + threadIdx.x) >> 5;   // row id in chunk
    int lane = threadIdx.x & 31;
    size_t off = (size_t)gw * 32 + lane;                       // 32 float4 per row
    float4 a = zr[off];
    float4 b = zv[off];
    float s = a.x * b.x + a.y * b.y + a.z * b.z + a.w * b.w;
    #pragma unroll
    for (int o = 16; o; o >>= 1) s += __shfl_xor_sync(0xffffffffu, s, o);
    if (lane == 0) dout[gw] = 1.0f - s;
}

// ---------------------------------------------------------------------------
// Batched block-wide sum over 128 threads (4 warps). All threads get results.
// ---------------------------------------------------------------------------
template<int K>
__device__ __forceinline__ void blockSumK(float* v, float (*red)[4])
{
    #pragma unroll
    for (int k = 0; k < K; k++)
        #pragma unroll
        for (int o = 16; o; o >>= 1)
            v[k] += __shfl_xor_sync(0xffffffffu, v[k], o);
    int w = threadIdx.x >> 5;
    if ((threadIdx.x & 31) == 0)
        #pragma unroll
        for (int k = 0; k < K; k++) red[k][w] = v[k];
    __syncthreads();
    #pragma unroll
    for (int k = 0; k < K; k++)
        v[k] = (red[k][0] + red[k][1]) + (red[k][2] + red[k][3]);
    __syncthreads();
}

// ---------------------------------------------------------------------------
// Kernel 2: one CTA (128 threads = S) per group; d from hot L2.
//  - single-pass moments: ONE blockSumK<8> for label sums + corr_loss
//  - stable rank: __match_any intra-warp + int4 scan of earlier warps only
//  - PARALLEL warp-scan prefix over 100 bins (no serial tid0 chain)
//  - violation loop float4-vectorized
//  - overall-last CTA finalizes out[0], out[1] (double precision).
// ---------------------------------------------------------------------------
__global__ void __launch_bounds__(128) group_kernel(
    const int* __restrict__ var_lens, const int* __restrict__ labels,
    float* __restrict__ out, int gbase)
{
    __shared__ int   sv[S];      // v (original order)
    __shared__ float sds[S];     // d sorted by v (stable)
    __shared__ int   se[S];      // tie-run end (exclusive) at sorted position
    __shared__ int   cnt[101];   // counting-sort bins
    __shared__ int   P[104];     // exclusive bin prefix; P[100] = S
    __shared__ float red[8][4];
    __shared__ int   wsum[4];    // scan warp partials
    __shared__ int   isLast;

    const int g    = gbase + blockIdx.x;
    const int tid  = threadIdx.x;     // == row index, all threads active
    const int w    = tid >> 5;
    const int lane = tid & 31;
    const float* dvec = out + 2;

    if (tid < 101) cnt[tid] = 0;
    __syncthreads();

    const int idx = g * S + tid;
    const float di = dvec[idx];              // L2-hot
    const int   v  = min(max(var_lens[idx], 0), 99);
    const int   lb = labels[idx];
    sv[tid] = v;
    atomicAdd(&cnt[v], 1);

    // ---- stable rank, intra-warp part ----
    unsigned m = __match_any_sync(0xffffffffu, v);
    int rank = __popc(m & ((1u << lane) - 1u));

    // ---- single-pass moments: 8 sums, one barrier pass (publishes sv/cnt) ---
    float vf = (float)v;
    float p1[8] = { lb == 0 ? di : 0.0f, lb == 1 ? di : 0.0f,
                    lb == 0 ? 1.0f : 0.0f,
                    vf, di, vf * vf, di * di, vf * di };
    blockSumK<8>(p1, red);
    float sb = p1[0], sp = p1[1], cb = p1[2];
    float sumv = p1[3], sumd = p1[4];
    float mv = sumv * (1.0f / S), md = sumd * (1.0f / S);
    float ssv = fmaxf(p1[5] - sumv * mv, 0.0f);   // Σ(v-mv)²
    float ssd = fmaxf(p1[6] - sumd * md, 0.0f);   // Σ(d-md)²
    float cov = p1[7] - sumv * md;                // Σ(v-mv)(d-md)
    float vs = sqrtf(ssv * (1.0f / (S - 1)));
    float ds = sqrtf(ssd * (1.0f / (S - 1)));
    float ia = 1.0f / (vs + EPS), ib = 1.0f / (ds + EPS);
    float corr = (ssv * ia * ia + ssd * ib * ib - 2.0f * cov * ia * ib) * (1.0f / S);
    if (!(vs > 0.0f && ds > 0.0f)) corr = 0.0f;

    // ---- rank, earlier-warp part: int4 scan of sv[0 .. 32w) ----
    {
        const int4* sv4 = (const int4*)sv;
        const int nch = w << 3;              // w * 8 chunks of 4
        for (int j4 = 0; j4 < nch; j4++) {
            int4 q = sv4[j4];
            rank += (q.x == v) + (q.y == v) + (q.z == v) + (q.w == v);
        }
    }

    // ---- parallel exclusive prefix over 100 bins (all 128 threads) ----
    {
        int c = (tid < 100) ? cnt[tid] : 0;
        int x = c;
        #pragma unroll
        for (int o = 1; o < 32; o <<= 1) {
            int y = __shfl_up_sync(0xffffffffu, x, o);
            if (lane >= o) x += y;
        }
        if (lane == 31) wsum[w] = x;
        __syncthreads();
        int off = 0;
        #pragma unroll
        for (int q = 0; q < 3; q++) off += (w > q) ? wsum[q] : 0;
        if (tid <= 100) P[tid] = x - c + off;   // exclusive; P[100] = S
    }
    __syncthreads();

    // ---- stable scatter ----
    {
        int pos = P[v] + rank;
        sds[pos] = di;
        se[pos]  = P[v + 1];   // end (exclusive) of this tie run
    }
    __syncthreads();

    // ---- neigh_viol + rank_loss ----
    float nv = (tid < S - 1) ? fmaxf(sds[tid] - sds[tid + 1] + K_MARGIN, 0.0f) : 0.0f;
    const int   e   = se[tid];
    const float ddi = sds[tid] + K_MARGIN;
    float viol = 0.0f;
    {
        int j = e;
        for (; (j & 3) && j < S; j++)            // head to 16B alignment
            viol += fmaxf(ddi - sds[j], 0.0f);
        const float4* s4 = (const float4*)sds;
        for (; j < S; j += 4) {
            float4 q = s4[j >> 2];
            viol += fmaxf(ddi - q.x, 0.0f) + fmaxf(ddi - q.y, 0.0f)
                  + fmaxf(ddi - q.z, 0.0f) + fmaxf(ddi - q.w, 0.0f);
        }
    }
    float p4[3] = { nv, (float)(S - e), viol };
    blockSumK<3>(p4, red);
    float neigh = p4[0] * (1.0f / (S - 1));
    float rankl = (p4[1] > 0.0f) ? p4[2] / p4[1] : 0.0f;

    if (tid == 0) {
        g_loss[g] = corr + neigh + rankl;
        g_sumb[g] = sb;
        g_sump[g] = sp;
        g_cntb[g] = (int)cb;
        __threadfence();
        int old = atomicAdd(&g_done, 1);
        isLast = (old == G - 1);
    }
    __syncthreads();

    // ---------------- overall-last CTA finalizes ----------------
    if (isLast) {
        __shared__ double shL[128], shB[128], shP[128];
        __shared__ long long shC[128];

        double aL = 0.0, aB = 0.0, aP = 0.0;
        long long cB = 0;
        #pragma unroll 4
        for (int q = tid; q < G; q += 128) {
            aL += (double)g_loss[q];
            aB += (double)g_sumb[q];
            aP += (double)g_sump[q];
            cB += (long long)g_cntb[q];
        }
        shL[tid] = aL; shB[tid] = aB; shP[tid] = aP; shC[tid] = cB;
        __syncthreads();
        #pragma unroll
        for (int s = 64; s > 0; s >>= 1) {
            if (tid < s) {
                shL[tid] += shL[tid + s];
                shB[tid] += shB[tid + s];
                shP[tid] += shP[tid + s];
                shC[tid] += shC[tid + s];
            }
            __syncthreads();
        }
        if (tid == 0) {
            long long nb = shC[0];
            long long np = (long long)NTOT - nb;
            double mb = shB[0] / (double)(nb > 1 ? nb : 1);
            double mp = shP[0] / (double)(np > 1 ? np : 1);
            double lcdd = (nb > 0 && np > 0) ? (MARGIN + mb - mp) : 0.0;
            if (lcdd < 0.0) lcdd = 0.0;
            out[0] = (float)lcdd;
            out[1] = (float)(shL[0] / (double)G);
            g_done = 0;            // reset for next graph replay
        }
    }
}

// ---------------------------------------------------------------------------
// Chunked two-stream pipeline: dot_c on s1 (high prio), group_c on s2.
// ---------------------------------------------------------------------------
extern "C" void kernel_launch(void* const* d_in, const int* in_sizes, int n_in,
                              void* d_out, int out_size)
{
    const float* zr       = (const float*)d_in[0];
    const float* zv       = (const float*)d_in[1];
    const int*   labels   = (const int*)d_in[2];
    // d_in[3] = groups (== i / S by construction, unused)
    const int*   var_lens = (const int*)d_in[4];
    float* out  = (float*)d_out;
    float* dvec = out + 2;

    cudaEventRecord(g_res.evFork, 0);
    cudaStreamWaitEvent(g_res.s1, g_res.evFork, 0);
    cudaStreamWaitEvent(g_res.s2, g_res.evFork, 0);

    for (int c = 0; c < NCHUNK; c++) {
        const float4* zrc = (const float4*)zr + (size_t)c * RCH * 32;
        const float4* zvc = (const float4*)zv + (size_t)c * RCH * 32;
        dot_kernel<<<RCH / 8, 256, 0, g_res.s1>>>(zrc, zvc, dvec + (size_t)c * RCH);
        cudaEventRecord(g_res.evDot[c], g_res.s1);

        cudaStreamWaitEvent(g_res.s2, g_res.evDot[c], 0);
        group_kernel<<<GCH, 128, 0, g_res.s2>>>(var_lens, labels, out, c * GCH);
    }

    cudaEventRecord(g_res.evJoin, g_res.s2);
    cudaStreamWaitEvent(0, g_res.evJoin, 0);
}